// round 2
// baseline (speedup 1.0000x reference)
#include <cuda_runtime.h>
#include <math.h>

#define N_TOK 4096
#define EMB   768
#define AED   512
#define NH    8
#define HD    64
#define KCL   32
#define THRS  1e-4f
#define EPSK  1e-6f
#define MAX_IT 100

// ---------------- device scratch ----------------
__device__ float g_WqF[EMB*AED];
__device__ float g_WkF[EMB*AED];
__device__ float g_WvF[EMB*AED];
__device__ float g_QH[N_TOK*AED];
__device__ float g_KH[N_TOK*AED];
__device__ float g_VH[N_TOK*AED];
__device__ float g_AO[N_TOK*AED];
__device__ float g_TR[N_TOK*AED];
__device__ float g_C[KCL*AED];
__device__ float g_Cnew[KCL*AED];
__device__ float g_Cacc[KCL*AED];
__device__ float g_asum[KCL];
__device__ float g_cn[KCL];
__device__ float g_xn[N_TOK];
__device__ float g_diff;
__device__ int   g_active;

// ---------------- generic tiled SGEMM: C = A @ op(B) (+bias) ----------------
// A: [M,K] row-major. TB=false: B [K,N]; TB=true: B [N,K] (C=A@B^T).
// M,N multiples of 64, K multiple of 16. 256 threads, 64x64 tile, 4x4 micro.
template<bool TB, bool BIAS>
__global__ void gemm64(const float* __restrict__ A, const float* __restrict__ B,
                       const float* __restrict__ bias, float* __restrict__ C,
                       int M, int N, int K) {
    __shared__ float As[16][65];
    __shared__ float Bs[16][65];
    const int tid = threadIdx.x;
    const int tx = tid & 15, ty = tid >> 4;
    const int m0 = blockIdx.y * 64, n0 = blockIdx.x * 64;

    float acc[4][4] = {};

    for (int k0 = 0; k0 < K; k0 += 16) {
        { // load A tile (transpose into As[k][m])
            int m = tid >> 2, kq = tid & 3;
            float4 v = *(const float4*)(A + (size_t)(m0 + m) * K + k0 + kq * 4);
            As[kq*4+0][m] = v.x; As[kq*4+1][m] = v.y;
            As[kq*4+2][m] = v.z; As[kq*4+3][m] = v.w;
        }
        if (TB) {
            int n = tid >> 2, kq = tid & 3;
            float4 v = *(const float4*)(B + (size_t)(n0 + n) * K + k0 + kq * 4);
            Bs[kq*4+0][n] = v.x; Bs[kq*4+1][n] = v.y;
            Bs[kq*4+2][n] = v.z; Bs[kq*4+3][n] = v.w;
        } else {
            int n4 = tid & 15, kk = tid >> 4;
            float4 v = *(const float4*)(B + (size_t)(k0 + kk) * N + n0 + n4 * 4);
            Bs[kk][n4*4+0] = v.x; Bs[kk][n4*4+1] = v.y;
            Bs[kk][n4*4+2] = v.z; Bs[kk][n4*4+3] = v.w;
        }
        __syncthreads();
        #pragma unroll
        for (int k = 0; k < 16; k++) {
            float a[4], b[4];
            #pragma unroll
            for (int i = 0; i < 4; i++) a[i] = As[k][ty*4 + i];
            #pragma unroll
            for (int j = 0; j < 4; j++) b[j] = Bs[k][tx*4 + j];
            #pragma unroll
            for (int i = 0; i < 4; i++)
                #pragma unroll
                for (int j = 0; j < 4; j++)
                    acc[i][j] += a[i] * b[j];
        }
        __syncthreads();
    }
    #pragma unroll
    for (int i = 0; i < 4; i++) {
        #pragma unroll
        for (int j = 0; j < 4; j++) {
            float v = acc[i][j];
            if (BIAS) v += bias[n0 + tx*4 + j];
            C[(size_t)(m0 + ty*4 + i) * N + n0 + tx*4 + j] = v;
        }
    }
}

// ---------------- flash attention (fp32, BM=BN=64, head dim 64) ----------------
// Q,K,V: [N_TOK, AED] with head h occupying columns [h*64, h*64+64).
#define ATTN_SMEM_FLOATS (3*64*64 + 64*66 + 3*64)
__global__ void attn_kernel(const float* __restrict__ Q, const float* __restrict__ K,
                            const float* __restrict__ V, float* __restrict__ O) {
    extern __shared__ float sm[];
    float* Qs = sm;                 // [64][64]
    float* Ks = Qs + 64*64;         // [64][64]
    float* Vs = Ks + 64*64;         // [64][64]
    float* Ss = Vs + 64*64;         // [64][66]
    float* mrow = Ss + 64*66;       // [64]
    float* lrow = mrow + 64;        // [64]
    float* arow = lrow + 64;        // [64]

    const int h = blockIdx.y;
    const int m0 = blockIdx.x * 64;
    const int tid = threadIdx.x;
    const int tx = tid & 15, ty = tid >> 4;

    for (int i = tid; i < 64*16; i += 256) {
        int r = i >> 4, c4 = i & 15;
        *(float4*)(Qs + r*64 + c4*4) =
            *(const float4*)(Q + (size_t)(m0 + r) * AED + h*HD + c4*4);
    }
    if (tid < 64) { mrow[tid] = -INFINITY; lrow[tid] = 0.f; }
    float acc[4][4] = {};
    __syncthreads();

    for (int kb = 0; kb < N_TOK; kb += 64) {
        for (int i = tid; i < 64*16; i += 256) {
            int r = i >> 4, c4 = i & 15;
            *(float4*)(Ks + r*64 + c4*4) =
                *(const float4*)(K + (size_t)(kb + r) * AED + h*HD + c4*4);
            *(float4*)(Vs + r*64 + c4*4) =
                *(const float4*)(V + (size_t)(kb + r) * AED + h*HD + c4*4);
        }
        __syncthreads();

        // S = Qs @ Ks^T * (1/8)
        float s[4][4] = {};
        #pragma unroll 8
        for (int k = 0; k < 64; k++) {
            float qa[4], kk[4];
            #pragma unroll
            for (int i = 0; i < 4; i++) qa[i] = Qs[(ty*4 + i)*64 + k];
            #pragma unroll
            for (int j = 0; j < 4; j++) kk[j] = Ks[(tx*4 + j)*64 + k];
            #pragma unroll
            for (int i = 0; i < 4; i++)
                #pragma unroll
                for (int j = 0; j < 4; j++)
                    s[i][j] += qa[i] * kk[j];
        }
        #pragma unroll
        for (int i = 0; i < 4; i++)
            #pragma unroll
            for (int j = 0; j < 4; j++)
                Ss[(ty*4 + i)*66 + tx*4 + j] = s[i][j] * 0.125f;
        __syncthreads();

        // online softmax per row (threads 0..63 each own one row)
        if (tid < 64) {
            float mold = mrow[tid];
            float mx = mold;
            #pragma unroll 8
            for (int c = 0; c < 64; c++) mx = fmaxf(mx, Ss[tid*66 + c]);
            float al = __expf(mold - mx);
            float sum = 0.f;
            #pragma unroll 8
            for (int c = 0; c < 64; c++) {
                float p = __expf(Ss[tid*66 + c] - mx);
                Ss[tid*66 + c] = p;
                sum += p;
            }
            lrow[tid] = lrow[tid] * al + sum;
            mrow[tid] = mx;
            arow[tid] = al;
        }
        __syncthreads();

        // O = O*alpha + P @ V
        float al_i[4];
        #pragma unroll
        for (int i = 0; i < 4; i++) al_i[i] = arow[ty*4 + i];
        #pragma unroll
        for (int i = 0; i < 4; i++)
            #pragma unroll
            for (int j = 0; j < 4; j++)
                acc[i][j] *= al_i[i];
        #pragma unroll 8
        for (int n = 0; n < 64; n++) {
            float p[4], v[4];
            #pragma unroll
            for (int i = 0; i < 4; i++) p[i] = Ss[(ty*4 + i)*66 + n];
            #pragma unroll
            for (int j = 0; j < 4; j++) v[j] = Vs[n*64 + tx*4 + j];
            #pragma unroll
            for (int i = 0; i < 4; i++)
                #pragma unroll
                for (int j = 0; j < 4; j++)
                    acc[i][j] += p[i] * v[j];
        }
        __syncthreads();
    }

    float li[4];
    #pragma unroll
    for (int i = 0; i < 4; i++) li[i] = lrow[ty*4 + i];
    #pragma unroll
    for (int i = 0; i < 4; i++)
        #pragma unroll
        for (int j = 0; j < 4; j++)
            O[(size_t)(m0 + ty*4 + i) * AED + h*HD + tx*4 + j] = acc[i][j] / li[i];
}

// ---------------- DKM helpers ----------------
__global__ void compute_xn(const float* __restrict__ X) {
    int w = threadIdx.x >> 5, lane = threadIdx.x & 31;
    int row = blockIdx.x * 8 + w;
    const float4* xr = (const float4*)(X + (size_t)row * AED);
    float p = 0.f;
    #pragma unroll
    for (int i = 0; i < 4; i++) {
        float4 v = xr[i*32 + lane];
        p += v.x*v.x + v.y*v.y + v.z*v.z + v.w*v.w;
    }
    #pragma unroll
    for (int off = 16; off >= 1; off >>= 1) p += __shfl_xor_sync(0xffffffffu, p, off);
    if (lane == 0) g_xn[row] = p;
}

__global__ void gather_init(const float* __restrict__ TR, const int* __restrict__ idx) {
    for (int i = blockIdx.x * blockDim.x + threadIdx.x; i < KCL*AED;
         i += gridDim.x * blockDim.x) {
        int r = i >> 9, c = i & 511;
        g_C[i] = TR[(size_t)idx[r] * AED + c];
    }
}

// one block, 256 threads: decide activity, update C<-Cnew, zero accumulators, compute cn
__global__ void dkm_prep(int first) {
    const int tid = threadIdx.x;
    __shared__ int act_s;
    if (tid == 0) {
        int act = first || (g_diff > THRS);
        g_active = act;
        act_s = act;
    }
    __syncthreads();
    if (!act_s) return;
    if (!first) {
        for (int i = tid; i < KCL*AED/4; i += 256)
            ((float4*)g_C)[i] = ((const float4*)g_Cnew)[i];
        __syncthreads();
    }
    for (int i = tid; i < KCL*AED/4; i += 256)
        ((float4*)g_Cacc)[i] = make_float4(0.f, 0.f, 0.f, 0.f);
    if (tid < KCL) g_asum[tid] = 0.f;
    // centroid norms: 8 threads per centroid
    int j = tid >> 3, s7 = tid & 7;
    float p = 0.f;
    const float4* cr = (const float4*)(g_C + (size_t)j * AED);
    #pragma unroll
    for (int i = 0; i < 16; i++) {
        float4 v = cr[s7*16 + i];
        p += v.x*v.x + v.y*v.y + v.z*v.z + v.w*v.w;
    }
    p += __shfl_xor_sync(0xffffffffu, p, 4);
    p += __shfl_xor_sync(0xffffffffu, p, 2);
    p += __shfl_xor_sync(0xffffffffu, p, 1);
    if (s7 == 0) g_cn[j] = p;
}

// 128 blocks x 256 threads, 32 rows per block.
// Phase 1: assignments a (softmax over 32 centroids); Phase 2: partial a^T X.
#define DKM_SMEM_FLOATS (KCL*AED + KCL*KCL)
__global__ void dkm_assign(const float* __restrict__ X, float* __restrict__ a_out) {
    if (!g_active) return;
    extern __shared__ float sm[];
    float* Cs  = sm;                // [32][512]
    float* a_s = Cs + KCL*AED;      // [32][32]
    __shared__ float cn_s[KCL];

    const int tid = threadIdx.x;
    const int lane = tid & 31, w = tid >> 5;
    const int rbase = blockIdx.x * 32;

    for (int i = tid; i < KCL*AED/4; i += 256)
        ((float4*)Cs)[i] = ((const float4*)g_C)[i];
    if (tid < KCL) cn_s[tid] = g_cn[tid];
    __syncthreads();

    float asum_part = 0.f;
    for (int rr = 0; rr < 4; rr++) {
        int row = rbase + w*4 + rr;
        float acc[32];
        #pragma unroll
        for (int j = 0; j < 32; j++) acc[j] = 0.f;
        const float4* Xr = (const float4*)(X + (size_t)row * AED);
        #pragma unroll
        for (int i = 0; i < 4; i++) {
            float4 x = Xr[i*32 + lane];
            #pragma unroll
            for (int j = 0; j < 32; j++) {
                float4 c = ((const float4*)(Cs + (size_t)j * AED))[i*32 + lane];
                acc[j] += x.x*c.x + x.y*c.y + x.z*c.z + x.w*c.w;
            }
        }
        // butterfly: lane l ends with full dot for centroid l in acc[0]
        #pragma unroll
        for (int off = 16; off >= 1; off >>= 1) {
            bool up = (lane & off) != 0;
            #pragma unroll
            for (int i2 = 0; i2 < 16; i2++) {
                if (i2 < off) {
                    float send = up ? acc[i2] : acc[i2 + off];
                    float other = __shfl_xor_sync(0xffffffffu, send, off);
                    float keep = up ? acc[i2 + off] : acc[i2];
                    acc[i2] = keep + other;
                }
            }
        }
        float dot = acc[0];
        float d2 = g_xn[row] + cn_s[lane] - 2.f * dot;
        float dist = sqrtf(fmaxf(d2, 0.f));
        float logit = -2.f * dist;   // -dist / TEMP, TEMP=0.5
        float mx = logit;
        #pragma unroll
        for (int off = 16; off >= 1; off >>= 1)
            mx = fmaxf(mx, __shfl_xor_sync(0xffffffffu, mx, off));
        float e = __expf(logit - mx);
        float ssum = e;
        #pragma unroll
        for (int off = 16; off >= 1; off >>= 1)
            ssum += __shfl_xor_sync(0xffffffffu, ssum, off);
        float aval = e / ssum;
        a_out[(size_t)row * KCL + lane] = aval;
        a_s[(w*4 + rr) * KCL + lane] = aval;
        asum_part += aval;
    }
    atomicAdd(&g_asum[lane], asum_part);
    __syncthreads();

    // Phase 2: Cacc[j][k] += sum_r a_s[r][j] * X[rbase+r][k]
    const int k4 = tid & 127;
    const int jg = tid >> 7;      // 0 or 1 -> j in [jg*16, jg*16+16)
    float4 accv[16];
    #pragma unroll
    for (int jj = 0; jj < 16; jj++) accv[jj] = make_float4(0.f, 0.f, 0.f, 0.f);
    for (int r = 0; r < 32; r++) {
        float4 x = ((const float4*)(X + (size_t)(rbase + r) * AED))[k4];
        #pragma unroll
        for (int jj = 0; jj < 16; jj++) {
            float av = a_s[r * KCL + jg*16 + jj];
            accv[jj].x += av * x.x;
            accv[jj].y += av * x.y;
            accv[jj].z += av * x.z;
            accv[jj].w += av * x.w;
        }
    }
    #pragma unroll
    for (int jj = 0; jj < 16; jj++) {
        float* dst = g_Cacc + (size_t)(jg*16 + jj) * AED + k4*4;
        atomicAdd(dst + 0, accv[jj].x);
        atomicAdd(dst + 1, accv[jj].y);
        atomicAdd(dst + 2, accv[jj].z);
        atomicAdd(dst + 3, accv[jj].w);
    }
}

// one block: Cnew = Cacc/(asum+eps), diff = sum|Cnew - C|
__global__ void dkm_finalize() {
    if (!g_active) return;
    const int tid = threadIdx.x;
    __shared__ float red[256];
    float dsum = 0.f;
    for (int i = tid; i < KCL*AED; i += 256) {
        int j = i >> 9;
        float cn_ = g_Cacc[i] / (g_asum[j] + EPSK);
        g_Cnew[i] = cn_;
        dsum += fabsf(cn_ - g_C[i]);
    }
    red[tid] = dsum;
    __syncthreads();
    for (int s = 128; s >= 1; s >>= 1) {
        if (tid < s) red[tid] += red[tid + s];
        __syncthreads();
    }
    if (tid == 0) g_diff = red[0];
}

__global__ void copy_out(float* __restrict__ out) {
    int i = blockIdx.x * 256 + threadIdx.x;
    out[i] = g_C[i];
}

// ---------------- launch ----------------
extern "C" void kernel_launch(void* const* d_in, const int* in_sizes, int n_in,
                              void* d_out, int out_size) {
    const float* X   = (const float*)d_in[0];
    const float* qw  = (const float*)d_in[1];
    const float* kw  = (const float*)d_in[2];
    const float* vw  = (const float*)d_in[3];
    const float* ipw = (const float*)d_in[4];
    const float* ipb = (const float*)d_in[5];
    const float* ow  = (const float*)d_in[6];
    const float* ob  = (const float*)d_in[7];
    const int*   idx = (const int*)d_in[8];

    float* out   = (float*)d_out;
    float* a_out = out + KCL*AED;   // C first, then a

    cudaFuncSetAttribute(attn_kernel, cudaFuncAttributeMaxDynamicSharedMemorySize,
                         ATTN_SMEM_FLOATS * 4);
    cudaFuncSetAttribute(dkm_assign, cudaFuncAttributeMaxDynamicSharedMemorySize,
                         DKM_SMEM_FLOATS * 4);

    // fused projection weights: W*F = (x->q weight) @ Wq^T etc.
    dim3 gW(AED/64, EMB/64);
    gemm64<true, false><<<gW, 256>>>(qw, ipw,               nullptr, g_WqF, EMB, AED, AED);
    gemm64<true, false><<<gW, 256>>>(kw, ipw + AED*AED,     nullptr, g_WkF, EMB, AED, AED);
    gemm64<true, false><<<gW, 256>>>(vw, ipw + 2*AED*AED,   nullptr, g_WvF, EMB, AED, AED);

    dim3 gP(AED/64, N_TOK/64);
    gemm64<false, true><<<gP, 256>>>(X, g_WqF, ipb,          g_QH, N_TOK, AED, EMB);
    gemm64<false, true><<<gP, 256>>>(X, g_WkF, ipb + AED,    g_KH, N_TOK, AED, EMB);
    gemm64<false, true><<<gP, 256>>>(X, g_WvF, ipb + 2*AED,  g_VH, N_TOK, AED, EMB);

    attn_kernel<<<dim3(N_TOK/64, NH), 256, ATTN_SMEM_FLOATS*4>>>(g_QH, g_KH, g_VH, g_AO);

    gemm64<true, true><<<gP, 256>>>(g_AO, ow, ob, g_TR, N_TOK, AED, AED);

    compute_xn<<<N_TOK/8, 256>>>(g_TR);
    gather_init<<<32, 256>>>(g_TR, idx);

    // DKM: initial step (it=0) + 100 masked body iterations, matching lax.scan
    for (int it = 0; it <= MAX_IT; it++) {
        dkm_prep<<<1, 256>>>(it == 0 ? 1 : 0);
        dkm_assign<<<N_TOK/32, 256, DKM_SMEM_FLOATS*4>>>(g_TR, a_out);
        dkm_finalize<<<1, 256>>>();
    }
    copy_out<<<KCL*AED/256, 256>>>(out);
}